// round 2
// baseline (speedup 1.0000x reference)
#include <cuda_runtime.h>
#include <cuda_bf16.h>
#include <cstdint>

// Problem constants
#define B_ROWS 1024
#define D_DIM  512
#define C_CLS  100000
#define S_SCALE 64.0f
#define M_MARG  0.5f
#define EPS_A   1e-07f

// GEMM tiling
#define BM 128
#define BN 128
#define BK 32
#define KS 36   // smem row stride in 32-bit words (conflict-free for frag loads)

// ---------------- scratch (no allocations allowed) ----------------
__device__ float g_xn[B_ROWS * D_DIM];   // normalized features (fp32)
__device__ float g_rowsum[B_ROWS];       // sum_c exp(S * wf[b,c])  (all classes)
__device__ float g_tgt[B_ROWS];          // fp32 true-class logit
__device__ int   g_y_is64;               // 1 if y_true is int64, 0 if int32

// ---------------- helpers ----------------
__device__ __forceinline__ unsigned f2tf32(float f) {
    unsigned u;
    asm("cvt.rna.tf32.f32 %0, %1;" : "=r"(u) : "f"(f));
    return u;
}

__device__ __forceinline__ void mma_tf32(float c[4], const unsigned a[4], const unsigned b[2]) {
    asm volatile(
        "mma.sync.aligned.m16n8k8.row.col.f32.tf32.tf32.f32 "
        "{%0,%1,%2,%3},{%4,%5,%6,%7},{%8,%9},{%0,%1,%2,%3};"
        : "+f"(c[0]), "+f"(c[1]), "+f"(c[2]), "+f"(c[3])
        : "r"(a[0]), "r"(a[1]), "r"(a[2]), "r"(a[3]),
          "r"(b[0]), "r"(b[1]));
}

// ---------------- kernel 0: detect y_true dtype ----------------
// If int64 (values < 2^31), every odd 32-bit word is 0. Reads only the first
// 64 int32 words — in bounds for either interpretation (buffer >= 4KB).
__global__ void detect_kernel(const int* __restrict__ y32) {
    int all_zero = 1;
    #pragma unroll
    for (int i = 0; i < 16; i++)
        if (y32[2 * i + 1] != 0) all_zero = 0;
    g_y_is64 = all_zero;
}

// ---------------- kernel 1: row L2-normalize + zero rowsum ----------------
__global__ __launch_bounds__(128) void norm_kernel(const float* __restrict__ X) {
    int b = blockIdx.x;
    const float* xr = X + (size_t)b * D_DIM;
    float s = 0.f;
    #pragma unroll
    for (int i = threadIdx.x; i < D_DIM; i += 128) {
        float v = xr[i];
        s += v * v;
    }
    #pragma unroll
    for (int o = 16; o > 0; o >>= 1) s += __shfl_xor_sync(0xffffffffu, s, o);
    __shared__ float red[4];
    int w = threadIdx.x >> 5;
    if ((threadIdx.x & 31) == 0) red[w] = s;
    __syncthreads();
    float tot = red[0] + red[1] + red[2] + red[3];
    float inv = 1.0f / fmaxf(sqrtf(tot), 1e-12f);
    #pragma unroll
    for (int i = threadIdx.x; i < D_DIM; i += 128)
        g_xn[(size_t)b * D_DIM + i] = xr[i] * inv;
    if (threadIdx.x == 0) g_rowsum[b] = 0.f;
}

// ---------------- kernel 2: fp32 true-class logit ----------------
__global__ __launch_bounds__(128) void tgt_kernel(const float* __restrict__ W,
                                                  const void* __restrict__ y) {
    int b = blockIdx.x;
    long long c;
    if (g_y_is64) c = ((const long long*)y)[b];
    else          c = (long long)((const int*)y)[b];
    // clamp so no interpretation can ever produce an OOB pointer
    if (c < 0) c = 0;
    if (c >= C_CLS) c = C_CLS - 1;
    const float* xr = g_xn + (size_t)b * D_DIM;
    const float* wr = W + (size_t)c * D_DIM;
    float s = 0.f;
    #pragma unroll
    for (int i = threadIdx.x; i < D_DIM; i += 128) s += xr[i] * wr[i];
    #pragma unroll
    for (int o = 16; o > 0; o >>= 1) s += __shfl_xor_sync(0xffffffffu, s, o);
    __shared__ float red[4];
    int w = threadIdx.x >> 5;
    if ((threadIdx.x & 31) == 0) red[w] = s;
    __syncthreads();
    if (threadIdx.x == 0) g_tgt[b] = red[0] + red[1] + red[2] + red[3];
}

// ---------------- kernel 3: fused tf32 GEMM + exp + row-sum ----------------
// Grid: ceil(C/BN) blocks of 256 threads. Each block owns a 128-class stripe
// and loops over all 8 row-tiles of B so W is read from DRAM once.
__global__ __launch_bounds__(256) void gemm_exp_kernel(const float* __restrict__ W) {
    __shared__ unsigned Xs[BM * KS];
    __shared__ unsigned Ws[BN * KS];

    const int tid  = threadIdx.x;
    const int lane = tid & 31;
    const int warp = tid >> 5;
    const int warpM = warp & 1;   // 2 warps in M
    const int warpN = warp >> 1;  // 4 warps in N
    const int colbase = blockIdx.x * BN;

    const int lr = tid >> 3;          // 0..31 load row within group of 32
    const int lk = (tid & 7) * 4;     // float4 column offset in the BK tile

    const int qrow = lane >> 2;       // 0..7
    const int qcol = lane & 3;        // 0..3

    for (int rt = 0; rt < B_ROWS / BM; rt++) {
        const int rowbase = rt * BM;
        float acc[4][4][4];
        #pragma unroll
        for (int mi = 0; mi < 4; mi++)
            #pragma unroll
            for (int ni = 0; ni < 4; ni++)
                #pragma unroll
                for (int r = 0; r < 4; r++) acc[mi][ni][r] = 0.f;

        for (int kt = 0; kt < D_DIM / BK; kt++) {
            __syncthreads();
            // --- load X tile: 128 x 32, converted to tf32 ---
            #pragma unroll
            for (int i = 0; i < 4; i++) {
                int r = lr + 32 * i;
                const float4 v = *(const float4*)(g_xn + (size_t)(rowbase + r) * D_DIM + kt * BK + lk);
                uint4 u;
                u.x = f2tf32(v.x); u.y = f2tf32(v.y); u.z = f2tf32(v.z); u.w = f2tf32(v.w);
                *(uint4*)(Xs + r * KS + lk) = u;
            }
            // --- load W tile: 128 x 32 (bounds-guarded), converted to tf32 ---
            #pragma unroll
            for (int i = 0; i < 4; i++) {
                int r = lr + 32 * i;
                int c = colbase + r;
                float4 v = make_float4(0.f, 0.f, 0.f, 0.f);
                if (c < C_CLS)
                    v = *(const float4*)(W + (size_t)c * D_DIM + kt * BK + lk);
                uint4 u;
                u.x = f2tf32(v.x); u.y = f2tf32(v.y); u.z = f2tf32(v.z); u.w = f2tf32(v.w);
                *(uint4*)(Ws + r * KS + lk) = u;
            }
            __syncthreads();

            // --- 4 k-steps of 8 ---
            #pragma unroll
            for (int ks = 0; ks < 4; ks++) {
                const int kb = ks * 8;
                unsigned a[4][4], bf[4][2];
                #pragma unroll
                for (int mi = 0; mi < 4; mi++) {
                    int row = warpM * 64 + mi * 16 + qrow;
                    a[mi][0] = Xs[row * KS + kb + qcol];
                    a[mi][1] = Xs[(row + 8) * KS + kb + qcol];
                    a[mi][2] = Xs[row * KS + kb + qcol + 4];
                    a[mi][3] = Xs[(row + 8) * KS + kb + qcol + 4];
                }
                #pragma unroll
                for (int ni = 0; ni < 4; ni++) {
                    int cc = warpN * 32 + ni * 8 + qrow;
                    bf[ni][0] = Ws[cc * KS + kb + qcol];
                    bf[ni][1] = Ws[cc * KS + kb + qcol + 4];
                }
                #pragma unroll
                for (int mi = 0; mi < 4; mi++)
                    #pragma unroll
                    for (int ni = 0; ni < 4; ni++)
                        mma_tf32(acc[mi][ni], a[mi], bf[ni]);
            }
        }

        // --- epilogue: exp + per-row partial sums ---
        #pragma unroll
        for (int mi = 0; mi < 4; mi++) {
            int r0 = rowbase + warpM * 64 + mi * 16 + qrow;
            int r1 = r0 + 8;
            float s0 = 0.f, s1 = 0.f;
            #pragma unroll
            for (int ni = 0; ni < 4; ni++) {
                int c0 = colbase + warpN * 32 + ni * 8 + 2 * qcol;
                int c1 = c0 + 1;
                if (c0 < C_CLS) {
                    s0 += __expf(S_SCALE * acc[mi][ni][0]);
                    s1 += __expf(S_SCALE * acc[mi][ni][2]);
                }
                if (c1 < C_CLS) {
                    s0 += __expf(S_SCALE * acc[mi][ni][1]);
                    s1 += __expf(S_SCALE * acc[mi][ni][3]);
                }
            }
            s0 += __shfl_xor_sync(0xffffffffu, s0, 1);
            s0 += __shfl_xor_sync(0xffffffffu, s0, 2);
            s1 += __shfl_xor_sync(0xffffffffu, s1, 1);
            s1 += __shfl_xor_sync(0xffffffffu, s1, 2);
            if (qcol == 0) {
                atomicAdd(g_rowsum + r0, s0);
                atomicAdd(g_rowsum + r1, s1);
            }
        }
    }
}

// ---------------- kernel 4: per-row loss + mean ----------------
__global__ __launch_bounds__(1024) void loss_kernel(float* __restrict__ out) {
    int b = threadIdx.x;
    float t = g_tgt[b];
    float tc = fminf(fmaxf(t, -1.0f + EPS_A), 1.0f - EPS_A);
    float num = S_SCALE * cosf(acosf(tc) + M_MARG);
    float excl = g_rowsum[b] - expf(S_SCALE * t);  // remove true-class term
    float denom = expf(num) + excl;
    float L = num - logf(denom);

    // block reduce (1024 threads = 32 warps)
    #pragma unroll
    for (int o = 16; o > 0; o >>= 1) L += __shfl_xor_sync(0xffffffffu, L, o);
    __shared__ float red[32];
    int w = threadIdx.x >> 5;
    if ((threadIdx.x & 31) == 0) red[w] = L;
    __syncthreads();
    if (w == 0) {
        float v = red[threadIdx.x & 31];
        #pragma unroll
        for (int o = 16; o > 0; o >>= 1) v += __shfl_xor_sync(0xffffffffu, v, o);
        if (threadIdx.x == 0) out[0] = -v / (float)B_ROWS;
    }
}

// ---------------- launch ----------------
extern "C" void kernel_launch(void* const* d_in, const int* in_sizes, int n_in,
                              void* d_out, int out_size) {
    const float* features = (const float*)d_in[0];  // [1024, 512]
    const float* W        = (const float*)d_in[1];  // [100000, 512]
    const void*  y_true   = d_in[2];                // [1024] int32 or int64
    float* out = (float*)d_out;

    detect_kernel<<<1, 1>>>((const int*)y_true);
    norm_kernel<<<B_ROWS, 128>>>(features);
    tgt_kernel<<<B_ROWS, 128>>>(W, y_true);
    const int grid = (C_CLS + BN - 1) / BN;  // 782
    gemm_exp_kernel<<<grid, 256>>>(W);
    loss_kernel<<<1, 1024>>>(out);
}

// round 3
// speedup vs baseline: 1.1769x; 1.1769x over previous
#include <cuda_runtime.h>
#include <cuda_bf16.h>
#include <cstdint>

// Problem constants
#define B_ROWS 1024
#define D_DIM  512
#define C_CLS  100000
#define S_SCALE 64.0f
#define M_MARG  0.5f
#define EPS_A   1e-07f

// GEMM tiling
#define BM 128
#define BN 128
#define BK 32
#define KS 36                      // smem row stride (words), conflict-free
#define STAGE_WORDS ((BM + BN) * KS)
#define SMEM_BYTES  (2 * STAGE_WORDS * 4)

// ---------------- scratch ----------------
__device__ float g_xn[B_ROWS * D_DIM];   // normalized + tf32-rounded features
__device__ float g_rowsum[B_ROWS];
__device__ float g_tgt[B_ROWS];
__device__ int   g_y_is64;

// ---------------- helpers ----------------
__device__ __forceinline__ float f2tf32f(float f) {
    unsigned u;
    asm("cvt.rna.tf32.f32 %0, %1;" : "=r"(u) : "f"(f));
    return __uint_as_float(u);
}

__device__ __forceinline__ void mma_tf32(float c[4], const unsigned a[4], const unsigned b[2]) {
    asm volatile(
        "mma.sync.aligned.m16n8k8.row.col.f32.tf32.tf32.f32 "
        "{%0,%1,%2,%3},{%4,%5,%6,%7},{%8,%9},{%0,%1,%2,%3};"
        : "+f"(c[0]), "+f"(c[1]), "+f"(c[2]), "+f"(c[3])
        : "r"(a[0]), "r"(a[1]), "r"(a[2]), "r"(a[3]),
          "r"(b[0]), "r"(b[1]));
}

__device__ __forceinline__ void cp16(unsigned dst, const float* src, bool valid) {
    int sz = valid ? 16 : 0;
    asm volatile("cp.async.ca.shared.global [%0], [%1], 16, %2;\n"
                 :: "r"(dst), "l"(src), "r"(sz));
}
__device__ __forceinline__ void cp_commit() {
    asm volatile("cp.async.commit_group;\n" ::: "memory");
}
__device__ __forceinline__ void cp_wait0() {
    asm volatile("cp.async.wait_group 0;\n" ::: "memory");
}

// ---------------- kernel 0: detect y_true dtype ----------------
__global__ void detect_kernel(const int* __restrict__ y32) {
    int all_zero = 1;
    #pragma unroll
    for (int i = 0; i < 16; i++)
        if (y32[2 * i + 1] != 0) all_zero = 0;
    g_y_is64 = all_zero;
}

// ---------------- kernel 1: L2-normalize rows, round to tf32, zero rowsum ----------------
__global__ __launch_bounds__(128) void norm_kernel(const float* __restrict__ X) {
    int b = blockIdx.x;
    const float* xr = X + (size_t)b * D_DIM;
    float s = 0.f;
    #pragma unroll
    for (int i = threadIdx.x; i < D_DIM; i += 128) {
        float v = xr[i];
        s += v * v;
    }
    #pragma unroll
    for (int o = 16; o > 0; o >>= 1) s += __shfl_xor_sync(0xffffffffu, s, o);
    __shared__ float red[4];
    int w = threadIdx.x >> 5;
    if ((threadIdx.x & 31) == 0) red[w] = s;
    __syncthreads();
    float tot = red[0] + red[1] + red[2] + red[3];
    float inv = 1.0f / fmaxf(sqrtf(tot), 1e-12f);
    #pragma unroll
    for (int i = threadIdx.x; i < D_DIM; i += 128)
        g_xn[(size_t)b * D_DIM + i] = f2tf32f(xr[i] * inv);
    if (threadIdx.x == 0) g_rowsum[b] = 0.f;
}

// ---------------- kernel 2: fp32 true-class logit ----------------
__global__ __launch_bounds__(128) void tgt_kernel(const float* __restrict__ W,
                                                  const void* __restrict__ y) {
    int b = blockIdx.x;
    long long c;
    if (g_y_is64) c = ((const long long*)y)[b];
    else          c = (long long)((const int*)y)[b];
    if (c < 0) c = 0;
    if (c >= C_CLS) c = C_CLS - 1;
    const float* xr = g_xn + (size_t)b * D_DIM;
    const float* wr = W + (size_t)c * D_DIM;
    float s = 0.f;
    #pragma unroll
    for (int i = threadIdx.x; i < D_DIM; i += 128) s += xr[i] * wr[i];
    #pragma unroll
    for (int o = 16; o > 0; o >>= 1) s += __shfl_xor_sync(0xffffffffu, s, o);
    __shared__ float red[4];
    int w = threadIdx.x >> 5;
    if ((threadIdx.x & 31) == 0) red[w] = s;
    __syncthreads();
    if (threadIdx.x == 0) g_tgt[b] = red[0] + red[1] + red[2] + red[3];
}

// ---------------- kernel 3: fused tf32 GEMM + exp + row-sum ----------------
// 2-stage cp.async pipeline; W fed as truncated tf32 (raw fp32 bits),
// X pre-rounded rna-tf32 in norm_kernel.
__global__ __launch_bounds__(256) void gemm_exp_kernel(const float* __restrict__ W) {
    extern __shared__ unsigned sm[];

    const int tid  = threadIdx.x;
    const int lane = tid & 31;
    const int warp = tid >> 5;
    const int warpM = warp & 1;
    const int warpN = warp >> 1;
    const int colbase = blockIdx.x * BN;

    const int lr  = tid >> 3;        // 0..31 (load row within group of 32)
    const int lkw = (tid & 7) * 4;   // word offset in BK tile

    const int qrow = lane >> 2;
    const int qcol = lane & 3;

    // per-thread smem store offsets (bytes → generic smem addr)
    unsigned smem_base_addr = (unsigned)__cvta_generic_to_shared(sm);

    // W row validity per load chunk (colbase fixed)
    bool wvalid[4];
    const float* wsrc_base[4];
    #pragma unroll
    for (int i = 0; i < 4; i++) {
        int c = colbase + lr + 32 * i;
        wvalid[i] = (c < C_CLS);
        wsrc_base[i] = W + (size_t)(wvalid[i] ? c : 0) * D_DIM + lkw;
    }

    // issue loads for (rowbase, kt) into stage st
    auto load_tiles = [&](int rowbase, int kt, int st) {
        unsigned xs = smem_base_addr + (unsigned)(st * STAGE_WORDS) * 4u;
        unsigned ws = xs + (unsigned)(BM * KS) * 4u;
        const float* xb = g_xn + (size_t)rowbase * D_DIM + kt * BK + lkw;
        #pragma unroll
        for (int i = 0; i < 4; i++) {
            int r = lr + 32 * i;
            cp16(xs + (unsigned)(r * KS + lkw) * 4u, xb + (size_t)r * D_DIM, true);
        }
        #pragma unroll
        for (int i = 0; i < 4; i++) {
            int r = lr + 32 * i;
            cp16(ws + (unsigned)(r * KS + lkw) * 4u, wsrc_base[i] + kt * BK, wvalid[i]);
        }
    };

    // prologue: rt=0, kt=0 into stage 0
    load_tiles(0, 0, 0);
    cp_commit();

    for (int rt = 0; rt < B_ROWS / BM; rt++) {
        const int rowbase = rt * BM;
        float acc[4][4][4];
        #pragma unroll
        for (int mi = 0; mi < 4; mi++)
            #pragma unroll
            for (int ni = 0; ni < 4; ni++)
                #pragma unroll
                for (int r = 0; r < 4; r++) acc[mi][ni][r] = 0.f;

        int s = 0;
        for (int kt = 0; kt < D_DIM / BK; kt++) {
            cp_wait0();
            __syncthreads();

            // prefetch next tile (next kt, or next rt's kt=0) into other stage
            if (kt + 1 < D_DIM / BK) {
                load_tiles(rowbase, kt + 1, s ^ 1);
                cp_commit();
            } else if (rt + 1 < B_ROWS / BM) {
                load_tiles(rowbase + BM, 0, s ^ 1);
                cp_commit();
            }

            const unsigned* Xs = sm + s * STAGE_WORDS;
            const unsigned* Ws = Xs + BM * KS;

            #pragma unroll
            for (int ks = 0; ks < 4; ks++) {
                const int kb = ks * 8;
                unsigned a[4][4], bf[4][2];
                #pragma unroll
                for (int mi = 0; mi < 4; mi++) {
                    int row = warpM * 64 + mi * 16 + qrow;
                    a[mi][0] = Xs[row * KS + kb + qcol];
                    a[mi][1] = Xs[(row + 8) * KS + kb + qcol];
                    a[mi][2] = Xs[row * KS + kb + qcol + 4];
                    a[mi][3] = Xs[(row + 8) * KS + kb + qcol + 4];
                }
                #pragma unroll
                for (int ni = 0; ni < 4; ni++) {
                    int cc = warpN * 32 + ni * 8 + qrow;
                    bf[ni][0] = Ws[cc * KS + kb + qcol];
                    bf[ni][1] = Ws[cc * KS + kb + qcol + 4];
                }
                #pragma unroll
                for (int mi = 0; mi < 4; mi++)
                    #pragma unroll
                    for (int ni = 0; ni < 4; ni++)
                        mma_tf32(acc[mi][ni], a[mi], bf[ni]);
            }
            s ^= 1;
        }

        // epilogue: exp + per-row partial sums (overlaps with prefetched next rt tile)
        #pragma unroll
        for (int mi = 0; mi < 4; mi++) {
            int r0 = rowbase + warpM * 64 + mi * 16 + qrow;
            int r1 = r0 + 8;
            float s0 = 0.f, s1 = 0.f;
            #pragma unroll
            for (int ni = 0; ni < 4; ni++) {
                int c0 = colbase + warpN * 32 + ni * 8 + 2 * qcol;
                int c1 = c0 + 1;
                if (c0 < C_CLS) {
                    s0 += __expf(S_SCALE * acc[mi][ni][0]);
                    s1 += __expf(S_SCALE * acc[mi][ni][2]);
                }
                if (c1 < C_CLS) {
                    s0 += __expf(S_SCALE * acc[mi][ni][1]);
                    s1 += __expf(S_SCALE * acc[mi][ni][3]);
                }
            }
            s0 += __shfl_xor_sync(0xffffffffu, s0, 1);
            s0 += __shfl_xor_sync(0xffffffffu, s0, 2);
            s1 += __shfl_xor_sync(0xffffffffu, s1, 1);
            s1 += __shfl_xor_sync(0xffffffffu, s1, 2);
            if (qcol == 0) {
                atomicAdd(g_rowsum + r0, s0);
                atomicAdd(g_rowsum + r1, s1);
            }
        }
    }
}

// ---------------- kernel 4: per-row loss + mean ----------------
__global__ __launch_bounds__(1024) void loss_kernel(float* __restrict__ out) {
    int b = threadIdx.x;
    float t = g_tgt[b];
    float tc = fminf(fmaxf(t, -1.0f + EPS_A), 1.0f - EPS_A);
    float num = S_SCALE * cosf(acosf(tc) + M_MARG);
    float excl = g_rowsum[b] - expf(S_SCALE * t);
    float denom = expf(num) + excl;
    float L = num - logf(denom);

    #pragma unroll
    for (int o = 16; o > 0; o >>= 1) L += __shfl_xor_sync(0xffffffffu, L, o);
    __shared__ float red[32];
    int w = threadIdx.x >> 5;
    if ((threadIdx.x & 31) == 0) red[w] = L;
    __syncthreads();
    if (w == 0) {
        float v = red[threadIdx.x & 31];
        #pragma unroll
        for (int o = 16; o > 0; o >>= 1) v += __shfl_xor_sync(0xffffffffu, v, o);
        if (threadIdx.x == 0) out[0] = -v / (float)B_ROWS;
    }
}

// ---------------- launch ----------------
extern "C" void kernel_launch(void* const* d_in, const int* in_sizes, int n_in,
                              void* d_out, int out_size) {
    const float* features = (const float*)d_in[0];
    const float* W        = (const float*)d_in[1];
    const void*  y_true   = d_in[2];
    float* out = (float*)d_out;

    cudaFuncSetAttribute(gemm_exp_kernel,
                         cudaFuncAttributeMaxDynamicSharedMemorySize, SMEM_BYTES);

    detect_kernel<<<1, 1>>>((const int*)y_true);
    norm_kernel<<<B_ROWS, 128>>>(features);
    tgt_kernel<<<B_ROWS, 128>>>(W, y_true);
    const int grid = (C_CLS + BN - 1) / BN;  // 782
    gemm_exp_kernel<<<grid, 256, SMEM_BYTES>>>(W);
    loss_kernel<<<1, 1024>>>(out);
}

// round 5
// speedup vs baseline: 1.7812x; 1.5134x over previous
#include <cuda_runtime.h>
#include <cuda_bf16.h>
#include <cstdint>

// ---------------- problem constants ----------------
#define B_ROWS 1024
#define D_DIM  512
#define C_CLS  100000
#define S_SCALE 64.0f
#define M_MARG  0.5f
#define EPS_A   1e-07f

// GEMM tiling: per-CTA 128 rows x 128 classes, K chunked by 64 (bf16)
#define BM 128
#define BN 128
#define BK 64
#define ROW_BYTES   144                        // 64 bf16 = 128B data + 16B pad
#define TILE_BYTES  (128 * ROW_BYTES)          // 18432
#define STAGE_BYTES (2 * TILE_BYTES)           // X + W
#define SMEM_BYTES  (2 * STAGE_BYTES + 256)

// ---------------- scratch ----------------
__device__ float          g_xn[B_ROWS * D_DIM];          // normalized features fp32
__device__ __nv_bfloat16  g_xbf[B_ROWS * D_DIM];         // normalized features bf16
__device__ __nv_bfloat16  g_wbf[(size_t)C_CLS * D_DIM];  // W in bf16
__device__ float          g_rowsum[B_ROWS];
__device__ float          g_tgt[B_ROWS];
__device__ int            g_y_is64;

// ---------------- helpers ----------------
__device__ __forceinline__ void ldsm_x4(unsigned r[4], unsigned addr) {
    asm volatile("ldmatrix.sync.aligned.m8n8.x4.shared.b16 {%0,%1,%2,%3}, [%4];"
                 : "=r"(r[0]), "=r"(r[1]), "=r"(r[2]), "=r"(r[3]) : "r"(addr));
}

__device__ __forceinline__ void mma_bf16(float c[4], const unsigned a[4], const unsigned b[2]) {
    asm volatile(
        "mma.sync.aligned.m16n8k16.row.col.f32.bf16.bf16.f32 "
        "{%0,%1,%2,%3},{%4,%5,%6,%7},{%8,%9},{%0,%1,%2,%3};"
        : "+f"(c[0]), "+f"(c[1]), "+f"(c[2]), "+f"(c[3])
        : "r"(a[0]), "r"(a[1]), "r"(a[2]), "r"(a[3]),
          "r"(b[0]), "r"(b[1]));
}

__device__ __forceinline__ void cp16(unsigned dst, const void* src, bool valid) {
    int sz = valid ? 16 : 0;
    asm volatile("cp.async.cg.shared.global [%0], [%1], 16, %2;\n"
                 :: "r"(dst), "l"(src), "r"(sz));
}
__device__ __forceinline__ void cp_commit() {
    asm volatile("cp.async.commit_group;\n" ::: "memory");
}
__device__ __forceinline__ void cp_wait0() {
    asm volatile("cp.async.wait_group 0;\n" ::: "memory");
}

// ---------------- kernel 0: detect y_true dtype ----------------
__global__ void detect_kernel(const int* __restrict__ y32) {
    int all_zero = 1;
    #pragma unroll
    for (int i = 0; i < 16; i++)
        if (y32[2 * i + 1] != 0) all_zero = 0;
    g_y_is64 = all_zero;
}

// ---------------- kernel 0b: convert W to bf16 ----------------
__global__ __launch_bounds__(256) void wconv_kernel(const float* __restrict__ W) {
    size_t i = ((size_t)blockIdx.x * 256 + threadIdx.x) * 4;   // 50000*256*4 = 51.2e6 exact
    float4 v = *(const float4*)(W + i);
    __nv_bfloat162 lo = __floats2bfloat162_rn(v.x, v.y);
    __nv_bfloat162 hi = __floats2bfloat162_rn(v.z, v.w);
    __nv_bfloat162* dst = (__nv_bfloat162*)(g_wbf + i);
    dst[0] = lo;
    dst[1] = hi;
}

// ---------------- kernel 1: L2-normalize rows (fp32 + bf16), zero rowsum ----------------
__global__ __launch_bounds__(128) void norm_kernel(const float* __restrict__ X) {
    int b = blockIdx.x;
    const float* xr = X + (size_t)b * D_DIM;
    float s = 0.f;
    #pragma unroll
    for (int i = threadIdx.x; i < D_DIM; i += 128) {
        float v = xr[i];
        s += v * v;
    }
    #pragma unroll
    for (int o = 16; o > 0; o >>= 1) s += __shfl_xor_sync(0xffffffffu, s, o);
    __shared__ float red[4];
    int w = threadIdx.x >> 5;
    if ((threadIdx.x & 31) == 0) red[w] = s;
    __syncthreads();
    float tot = red[0] + red[1] + red[2] + red[3];
    float inv = 1.0f / fmaxf(sqrtf(tot), 1e-12f);
    #pragma unroll
    for (int i = threadIdx.x; i < D_DIM; i += 128) {
        float v = xr[i] * inv;
        g_xn[(size_t)b * D_DIM + i] = v;
        g_xbf[(size_t)b * D_DIM + i] = __float2bfloat16_rn(v);
    }
    if (threadIdx.x == 0) g_rowsum[b] = 0.f;
}

// ---------------- kernel 2: fp32 true-class logit ----------------
__global__ __launch_bounds__(128) void tgt_kernel(const float* __restrict__ W,
                                                  const void* __restrict__ y) {
    int b = blockIdx.x;
    long long c;
    if (g_y_is64) c = ((const long long*)y)[b];
    else          c = (long long)((const int*)y)[b];
    if (c < 0) c = 0;
    if (c >= C_CLS) c = C_CLS - 1;
    const float* xr = g_xn + (size_t)b * D_DIM;
    const float* wr = W + (size_t)c * D_DIM;
    float s = 0.f;
    #pragma unroll
    for (int i = threadIdx.x; i < D_DIM; i += 128) s += xr[i] * wr[i];
    #pragma unroll
    for (int o = 16; o > 0; o >>= 1) s += __shfl_xor_sync(0xffffffffu, s, o);
    __shared__ float red[4];
    int w = threadIdx.x >> 5;
    if ((threadIdx.x & 31) == 0) red[w] = s;
    __syncthreads();
    if (threadIdx.x == 0) g_tgt[b] = red[0] + red[1] + red[2] + red[3];
}

// ---------------- kernel 3: fused bf16 GEMM (ldmatrix + mma.m16n8k16) + exp + row-sum ----------------
__global__ __launch_bounds__(256, 2) void gemm_exp_kernel() {
    extern __shared__ char sm_raw[];

    const int tid  = threadIdx.x;
    const int lane = tid & 31;
    const int warp = tid >> 5;
    const int warpM = warp & 1;    // 2 warps over M (64 rows each)
    const int warpN = warp >> 1;   // 4 warps over N (32 cols each)
    const int colbase = blockIdx.x * BN;

    unsigned sbase = (unsigned)__cvta_generic_to_shared(sm_raw);
    sbase = (sbase + 255u) & ~255u;

    const int lr  = tid >> 3;      // load row 0..31
    const int seg = tid & 7;       // 16B segment (8 per 128B row)

    bool wvalid[4];
    const __nv_bfloat16* wrow[4];
    #pragma unroll
    for (int i = 0; i < 4; i++) {
        int c = colbase + lr + 32 * i;
        wvalid[i] = (c < C_CLS);
        wrow[i] = g_wbf + (size_t)(wvalid[i] ? c : 0) * D_DIM + seg * 8;
    }

    auto load_chunk = [&](int g, int st) {
        const int rt = g >> 3, kt = g & 7;
        const unsigned xs = sbase + (unsigned)st * (unsigned)STAGE_BYTES;
        const unsigned ws = xs + (unsigned)TILE_BYTES;
        const __nv_bfloat16* xb = g_xbf + (size_t)(rt * BM) * D_DIM + kt * BK + seg * 8;
        #pragma unroll
        for (int i = 0; i < 4; i++) {
            int r = lr + 32 * i;
            unsigned off = (unsigned)(r * ROW_BYTES + seg * 16);
            cp16(xs + off, xb + (size_t)r * D_DIM, true);
            cp16(ws + off, wrow[i] + kt * BK, wvalid[i]);
        }
    };

    const int lrow = lane & 15;
    const int lhi  = (lane >> 4) * 16;
    const int qrow = lane >> 2;
    const int qcol = lane & 3;

    load_chunk(0, 0);
    cp_commit();

    float acc[4][4][4];
    #pragma unroll
    for (int mi = 0; mi < 4; mi++)
        #pragma unroll
        for (int ni = 0; ni < 4; ni++)
            #pragma unroll
            for (int r = 0; r < 4; r++) acc[mi][ni][r] = 0.f;

    for (int g = 0; g < 64; g++) {
        const int s = g & 1;

        cp_wait0();
        __syncthreads();

        if (g + 1 < 64) {
            load_chunk(g + 1, s ^ 1);
            cp_commit();
        }

        const unsigned xs = sbase + (unsigned)s * (unsigned)STAGE_BYTES;
        const unsigned ws = xs + (unsigned)TILE_BYTES;

        #pragma unroll
        for (int ks = 0; ks < 4; ks++) {
            const int kb = ks * 32;   // k16 step = 32 bytes
            unsigned a[4][4];
            unsigned bq[2][4];
            #pragma unroll
            for (int mi = 0; mi < 4; mi++)
                ldsm_x4(a[mi], xs + (unsigned)((warpM * 64 + mi * 16 + lrow) * ROW_BYTES + kb + lhi));
            #pragma unroll
            for (int p = 0; p < 2; p++)
                ldsm_x4(bq[p], ws + (unsigned)((warpN * 32 + p * 16 + lrow) * ROW_BYTES + kb + lhi));
            #pragma unroll
            for (int mi = 0; mi < 4; mi++) {
                #pragma unroll
                for (int p = 0; p < 2; p++) {
                    unsigned b0[2] = { bq[p][0], bq[p][2] };
                    unsigned b1[2] = { bq[p][1], bq[p][3] };
                    mma_bf16(acc[mi][2 * p + 0], a[mi], b0);
                    mma_bf16(acc[mi][2 * p + 1], a[mi], b1);
                }
            }
        }

        if ((g & 7) == 7) {
            const int rt = g >> 3;
            #pragma unroll
            for (int mi = 0; mi < 4; mi++) {
                int r0 = rt * BM + warpM * 64 + mi * 16 + qrow;
                int r1 = r0 + 8;
                float s0 = 0.f, s1 = 0.f;
                #pragma unroll
                for (int ni = 0; ni < 4; ni++) {
                    int c0 = colbase + warpN * 32 + ni * 8 + 2 * qcol;
                    int c1 = c0 + 1;
                    if (c0 < C_CLS) {
                        s0 += __expf(S_SCALE * acc[mi][ni][0]);
                        s1 += __expf(S_SCALE * acc[mi][ni][2]);
                    }
                    if (c1 < C_CLS) {
                        s0 += __expf(S_SCALE * acc[mi][ni][1]);
                        s1 += __expf(S_SCALE * acc[mi][ni][3]);
                    }
                    #pragma unroll
                    for (int r = 0; r < 4; r++) acc[mi][ni][r] = 0.f;
                }
                s0 += __shfl_xor_sync(0xffffffffu, s0, 1);
                s0 += __shfl_xor_sync(0xffffffffu, s0, 2);
                s1 += __shfl_xor_sync(0xffffffffu, s1, 1);
                s1 += __shfl_xor_sync(0xffffffffu, s1, 2);
                if (qcol == 0) {
                    atomicAdd(g_rowsum + r0, s0);
                    atomicAdd(g_rowsum + r1, s1);
                }
            }
        }
    }
}

// ---------------- kernel 4: per-row loss + mean ----------------
__global__ __launch_bounds__(1024) void loss_kernel(float* __restrict__ out) {
    int b = threadIdx.x;
    float t = g_tgt[b];
    float tc = fminf(fmaxf(t, -1.0f + EPS_A), 1.0f - EPS_A);
    float num = S_SCALE * cosf(acosf(tc) + M_MARG);
    float excl = g_rowsum[b] - expf(S_SCALE * t);
    float denom = expf(num) + excl;
    float L = num - logf(denom);

    #pragma unroll
    for (int o = 16; o > 0; o >>= 1) L += __shfl_xor_sync(0xffffffffu, L, o);
    __shared__ float red[32];
    int w = threadIdx.x >> 5;
    if ((threadIdx.x & 31) == 0) red[w] = L;
    __syncthreads();
    if (w == 0) {
        float v = red[threadIdx.x & 31];
        #pragma unroll
        for (int o = 16; o > 0; o >>= 1) v += __shfl_xor_sync(0xffffffffu, v, o);
        if (threadIdx.x == 0) out[0] = -v / (float)B_ROWS;
    }
}

// ---------------- launch ----------------
extern "C" void kernel_launch(void* const* d_in, const int* in_sizes, int n_in,
                              void* d_out, int out_size) {
    const float* features = (const float*)d_in[0];
    const float* W        = (const float*)d_in[1];
    const void*  y_true   = d_in[2];
    float* out = (float*)d_out;

    cudaFuncSetAttribute(gemm_exp_kernel,
                         cudaFuncAttributeMaxDynamicSharedMemorySize, SMEM_BYTES);

    detect_kernel<<<1, 1>>>((const int*)y_true);
    wconv_kernel<<<50000, 256>>>(W);
    norm_kernel<<<B_ROWS, 128>>>(features);
    tgt_kernel<<<B_ROWS, 128>>>(W, y_true);
    const int grid = (C_CLS + BN - 1) / BN;  // 782
    gemm_exp_kernel<<<grid, 256, SMEM_BYTES>>>();
    loss_kernel<<<1, 1024>>>(out);
}